// round 7
// baseline (speedup 1.0000x reference)
#include <cuda_runtime.h>
#include <cuda_bf16.h>
#include <math.h>
#include <stdint.h>

#define NBATCH  128
#define NH_     256
#define NHC_    128
#define NU_     64
#define NY_     64
#define NCHUNK  32
#define TCH     32

// ---- smem layout (bytes) ----------------------------------------------------
#define SB_STR   72      // bf16 words per row for U/B' tiles
#define SW_STR   264     // bf16 words per row for W tiles
#define SX_STR   264     // fp32/packed words per row for BuX tile

#define OFF_BPHI 0                    // B' hi  [256][72] bf16 (rows permuted)
#define OFF_BPLO 36864                // B' lo
#define OFF_WHI  73728                // W hi   [64][264] bf16 (k permuted)
#define OFF_WLO  107520               // W lo
#define OFF_UHI  141312               // U hi   [32][72] bf16
#define OFF_ULO  145920               // U lo
#define OFF_BUX0 150528               // BuX buf0 [32][264] fp32/packed
#define OFF_BUX1 184320               // BuX buf1
#define OFF_X0   218112               // 256 fp32 (permuted layout)
#define SMEM_TOTAL 219136

// ---- helpers ----------------------------------------------------------------
__device__ __forceinline__ uint32_t sptr(const void* p) {
    return (uint32_t)__cvta_generic_to_shared(p);
}
__device__ __forceinline__ int permh(int h) {       // hidden-dim permutation
    return (h < NHC_) ? 2 * h : 2 * (h - NHC_) + 1;
}
__device__ __forceinline__ void split2(float a0, float a1, uint32_t& hi, uint32_t& lo) {
    __nv_bfloat16 h0 = __float2bfloat16_rn(a0);
    __nv_bfloat16 h1 = __float2bfloat16_rn(a1);
    __nv_bfloat16 l0 = __float2bfloat16_rn(a0 - __bfloat162float(h0));
    __nv_bfloat16 l1 = __float2bfloat16_rn(a1 - __bfloat162float(h1));
    hi = ((uint32_t)__bfloat16_as_ushort(h1) << 16) | __bfloat16_as_ushort(h0);
    lo = ((uint32_t)__bfloat16_as_ushort(l1) << 16) | __bfloat16_as_ushort(l0);
}
__device__ __forceinline__ void split1(float a, uint16_t& hi, uint16_t& lo) {
    __nv_bfloat16 h = __float2bfloat16_rn(a);
    __nv_bfloat16 l = __float2bfloat16_rn(a - __bfloat162float(h));
    hi = __bfloat16_as_ushort(h);
    lo = __bfloat16_as_ushort(l);
}
__device__ __forceinline__ uint32_t pack_hl(float v) {
    __nv_bfloat16 h = __float2bfloat16_rn(v);
    __nv_bfloat16 l = __float2bfloat16_rn(v - __bfloat162float(h));
    return ((uint32_t)__bfloat16_as_ushort(h) << 16) | __bfloat16_as_ushort(l);
}
__device__ __forceinline__ void mma_bf16(float* c, const uint32_t* a, const uint32_t* b) {
    asm volatile(
        "mma.sync.aligned.m16n8k16.row.col.f32.bf16.bf16.f32 "
        "{%0,%1,%2,%3}, {%4,%5,%6,%7}, {%8,%9}, {%0,%1,%2,%3};"
        : "+f"(c[0]), "+f"(c[1]), "+f"(c[2]), "+f"(c[3])
        : "r"(a[0]), "r"(a[1]), "r"(a[2]), "r"(a[3]), "r"(b[0]), "r"(b[1]));
}
#define LDSM_X4(r0, r1, r2, r3, addr)                                        \
    asm volatile("ldmatrix.sync.aligned.m8n8.x4.shared.b16 {%0,%1,%2,%3}, [%4];" \
                 : "=r"(r0), "=r"(r1), "=r"(r2), "=r"(r3) : "r"(addr))
#define BAR_SYNC(id)   asm volatile("bar.sync %0, 512;"   :: "r"(id) : "memory")
#define BAR_ARRIVE(id) asm volatile("bar.arrive %0, 512;" :: "r"(id) : "memory")
#define BAR_P()        asm volatile("bar.sync 1, 256;" ::: "memory")

// ---- fused warp-specialized kernel ------------------------------------------
__global__ void __launch_bounds__(512, 1)
k_fused(const float* __restrict__ y0,   const float* __restrict__ U,
        const float* __restrict__ lre,  const float* __restrict__ lim,
        const float* __restrict__ B,    const float* __restrict__ W_y2x,
        const float* __restrict__ b_y2x,const float* __restrict__ W_x2y,
        const float* __restrict__ b_x2y,float* __restrict__ Y) {
    extern __shared__ char sm[];
    int tid  = threadIdx.x;
    int b    = blockIdx.x;
    int lane = tid & 31;
    int g = lane >> 2, tg = lane & 3;
    int j8 = lane >> 3, r8 = lane & 7;

    // ======== init: B' = B*nf, split, rows permuted (512 thr, half row each) ==
    {
        int h    = tid >> 1;
        int half = tid & 1;
        int n    = permh(h);
        int hc   = h & (NHC_ - 1);
        float a  = fabsf(__ldg(lre + hc));
        float nf = sqrtf(1.0f - expf(-2.0f * a));
        const float4* src = reinterpret_cast<const float4*>(B + h * NU_ + half * 32);
        #pragma unroll
        for (int q = 0; q < 8; q++) {
            float4 v = __ldg(src + q);
            v.x *= nf; v.y *= nf; v.z *= nf; v.w *= nf;
            uint32_t h01, l01, h23, l23;
            split2(v.x, v.y, h01, l01);
            split2(v.z, v.w, h23, l23);
            int k = half * 32 + q * 4;
            *(uint32_t*)(sm + OFF_BPHI + (n * SB_STR + k    ) * 2) = h01;
            *(uint32_t*)(sm + OFF_BPHI + (n * SB_STR + k + 2) * 2) = h23;
            *(uint32_t*)(sm + OFF_BPLO + (n * SB_STR + k    ) * 2) = l01;
            *(uint32_t*)(sm + OFF_BPLO + (n * SB_STR + k + 2) * 2) = l23;
        }
    }
    // ======== init: W planes, k permuted (scalar b16 stores, init-only) ======
    {
        int n    = tid >> 3;
        int part = tid & 7;
        const float4* src = reinterpret_cast<const float4*>(W_x2y + n * NH_ + part * 32);
        #pragma unroll
        for (int q = 0; q < 8; q++) {
            float4 v = __ldg(src + q);
            float vv[4] = {v.x, v.y, v.z, v.w};
            #pragma unroll
            for (int e = 0; e < 4; e++) {
                int oldk = part * 32 + q * 4 + e;
                int newk = permh(oldk);
                uint16_t hi, lo;
                split1(vv[e], hi, lo);
                *(uint16_t*)(sm + OFF_WHI + (n * SW_STR + newk) * 2) = hi;
                *(uint16_t*)(sm + OFF_WLO + (n * SW_STR + newk) * 2) = lo;
            }
        }
    }
    // ======== init: x0 (permuted store) ========
    if (tid < NH_) {
        float acc = __ldg(b_y2x + tid);
        const float* w = W_y2x + tid * NY_;
        const float* y = y0 + b * NY_;
        #pragma unroll
        for (int k = 0; k < NY_; k++) acc = fmaf(__ldg(y + k), __ldg(w + k), acc);
        ((float*)(sm + OFF_X0))[permh(tid)] = acc;
    }

    // ======== producer U(0) prefetch ========
    int urow = (tid & 255) >> 3, uq = tid & 7;
    float4 ureg[2];
    if (tid < 256) {
        const float4* src = reinterpret_cast<const float4*>(
            U + ((size_t)urow * NBATCH + b) * NU_ + uq * 8);
        ureg[0] = __ldg(src);
        ureg[1] = __ldg(src + 1);
    }
    __syncthreads();

    if (tid < 256) {
        // =================== PRODUCER (warps 0-7) ===================
        float slr = 0.f, sli = 0.f, czr = 0.f, czi = 0.f;
        if (tid < NHC_) {
            float a  = fabsf(__ldg(lre + tid));
            float rr_ = expf(-a);
            float th = 1.5707963267948966f * __ldg(lim + tid);
            slr = rr_ * cosf(th);
            sli = rr_ * sinf(th);
            float2 x0v = ((const float2*)(sm + OFF_X0))[tid];
            czr = x0v.x; czi = x0v.y;
        }
        int warp = tid >> 5;
        int wn0  = warp * 32;

        for (int c = 0; c < NCHUNK; c++) {
            int buf = c & 1;
            char* bux_c = sm + (buf ? OFF_BUX1 : OFF_BUX0);
            BAR_SYNC(4 + buf);               // wait buffer empty

            // STS U(c) split planes
            #pragma unroll
            for (int j = 0; j < 2; j++) {
                float4 v = ureg[j];
                uint32_t h01, l01, h23, l23;
                split2(v.x, v.y, h01, l01);
                split2(v.z, v.w, h23, l23);
                int k = uq * 8 + j * 4;
                *(uint32_t*)(sm + OFF_UHI + (urow * SB_STR + k    ) * 2) = h01;
                *(uint32_t*)(sm + OFF_UHI + (urow * SB_STR + k + 2) * 2) = h23;
                *(uint32_t*)(sm + OFF_ULO + (urow * SB_STR + k    ) * 2) = l01;
                *(uint32_t*)(sm + OFF_ULO + (urow * SB_STR + k + 2) * 2) = l23;
            }
            BAR_P();
            if (c < NCHUNK - 1) {
                const float4* src = reinterpret_cast<const float4*>(
                    U + ((size_t)((c + 1) * TCH + urow) * NBATCH + b) * NU_ + uq * 8);
                ureg[0] = __ldg(src);
                ureg[1] = __ldg(src + 1);
            }

            // ---- Bu GEMM: M=32, warp n-slice 32, K=64 ----
            float C[2][4][4];
            #pragma unroll
            for (int mt = 0; mt < 2; mt++)
                #pragma unroll
                for (int nt = 0; nt < 4; nt++)
                    #pragma unroll
                    for (int i = 0; i < 4; i++) C[mt][nt][i] = 0.0f;

            #pragma unroll
            for (int k0 = 0; k0 < 64; k0 += 16) {
                int arow = (j8 & 1) * 8 + r8;
                int acol = k0 + (j8 >> 1) * 8;
                uint32_t Ah[2][4], Al[2][4];
                #pragma unroll
                for (int mt = 0; mt < 2; mt++) {
                    uint32_t ah = sptr(sm + OFF_UHI + ((mt * 16 + arow) * SB_STR + acol) * 2);
                    uint32_t al = sptr(sm + OFF_ULO + ((mt * 16 + arow) * SB_STR + acol) * 2);
                    LDSM_X4(Ah[mt][0], Ah[mt][1], Ah[mt][2], Ah[mt][3], ah);
                    LDSM_X4(Al[mt][0], Al[mt][1], Al[mt][2], Al[mt][3], al);
                }
                uint32_t Bh[4][2], Bl[4][2];
                #pragma unroll
                for (int ntp = 0; ntp < 2; ntp++) {
                    int nrow = wn0 + (ntp * 2 + (j8 >> 1)) * 8 + r8;
                    int bcol = k0 + (j8 & 1) * 8;
                    uint32_t bh = sptr(sm + OFF_BPHI + (nrow * SB_STR + bcol) * 2);
                    uint32_t bl = sptr(sm + OFF_BPLO + (nrow * SB_STR + bcol) * 2);
                    LDSM_X4(Bh[ntp*2][0], Bh[ntp*2][1], Bh[ntp*2+1][0], Bh[ntp*2+1][1], bh);
                    LDSM_X4(Bl[ntp*2][0], Bl[ntp*2][1], Bl[ntp*2+1][0], Bl[ntp*2+1][1], bl);
                }
                #pragma unroll
                for (int mt = 0; mt < 2; mt++)
                    #pragma unroll
                    for (int nt = 0; nt < 4; nt++) {
                        mma_bf16(C[mt][nt], Ah[mt], Bh[nt]);
                        mma_bf16(C[mt][nt], Ah[mt], Bl[nt]);
                        mma_bf16(C[mt][nt], Al[mt], Bh[nt]);
                    }
            }
            // epilogue -> BuX fp32
            float* bx = (float*)bux_c;
            #pragma unroll
            for (int mt = 0; mt < 2; mt++)
                #pragma unroll
                for (int nt = 0; nt < 4; nt++) {
                    int r = mt * 16 + g;
                    int n = wn0 + nt * 8 + 2 * tg;
                    *(float2*)&bx[r * SX_STR + n]       = make_float2(C[mt][nt][0], C[mt][nt][1]);
                    *(float2*)&bx[(r + 8) * SX_STR + n] = make_float2(C[mt][nt][2], C[mt][nt][3]);
                }
            BAR_P();

            // ---- scan (warps 0-3, adjacent re/im), write packed in place ----
            if (tid < NHC_) {
                uint32_t* bxu = (uint32_t*)bux_c;
                float zr = czr, zi = czi;
                #pragma unroll 4
                for (int t = 0; t < TCH; t++) {
                    float2 u = *(const float2*)&bx[t * SX_STR + 2 * tid];
                    float nr = fmaf(slr, zr, fmaf(-sli, zi, u.x));
                    float ni = fmaf(sli, zr, fmaf( slr, zi, u.y));
                    zr = nr; zi = ni;
                    *(uint2*)&bxu[t * SX_STR + 2 * tid] =
                        make_uint2(pack_hl(zr), pack_hl(zi));
                }
                czr = zr; czi = zi;
            }
            BAR_ARRIVE(2 + buf);             // buffer full
        }
    } else {
        // =================== CONSUMER (warps 8-15) ===================
        int qw  = (tid >> 5) - 8;
        int wm0 = (qw >> 2) * 16;
        int wn0 = (qw & 3) * 16;
        BAR_ARRIVE(4);
        BAR_ARRIVE(5);
        float bias0[2], bias1[2];
        #pragma unroll
        for (int nt = 0; nt < 2; nt++) {
            bias0[nt] = __ldg(b_x2y + wn0 + nt * 8 + 2 * tg);
            bias1[nt] = __ldg(b_x2y + wn0 + nt * 8 + 2 * tg + 1);
        }

        for (int c = 0; c < NCHUNK; c++) {
            int buf = c & 1;
            const uint32_t* bxu = (const uint32_t*)(sm + (buf ? OFF_BUX1 : OFF_BUX0));
            BAR_SYNC(2 + buf);               // wait full

            float C[2][4];
            #pragma unroll
            for (int nt = 0; nt < 2; nt++) {
                C[nt][0] = bias0[nt]; C[nt][1] = bias1[nt];
                C[nt][2] = bias0[nt]; C[nt][3] = bias1[nt];
            }
            #pragma unroll 4
            for (int k0 = 0; k0 < 256; k0 += 16) {
                uint32_t Ah[4], Al[4];
                #pragma unroll
                for (int pos = 0; pos < 4; pos++) {
                    int rr = wm0 + g + ((pos & 1) ? 8 : 0);
                    int kk = k0 + 2 * tg + ((pos & 2) ? 8 : 0);
                    uint2 w = *(const uint2*)&bxu[rr * SX_STR + kk];
                    Ah[pos] = __byte_perm(w.x, w.y, 0x7632);
                    Al[pos] = __byte_perm(w.x, w.y, 0x5410);
                }
                uint32_t Bh[2][2], Bl[2][2];
                {
                    int nrow = wn0 + (j8 >> 1) * 8 + r8;
                    int bcol = k0 + (j8 & 1) * 8;
                    uint32_t bh = sptr(sm + OFF_WHI + (nrow * SW_STR + bcol) * 2);
                    uint32_t bl = sptr(sm + OFF_WLO + (nrow * SW_STR + bcol) * 2);
                    LDSM_X4(Bh[0][0], Bh[0][1], Bh[1][0], Bh[1][1], bh);
                    LDSM_X4(Bl[0][0], Bl[0][1], Bl[1][0], Bl[1][1], bl);
                }
                #pragma unroll
                for (int nt = 0; nt < 2; nt++) {
                    mma_bf16(C[nt], Ah, Bh[nt]);
                    mma_bf16(C[nt], Ah, Bl[nt]);
                    mma_bf16(C[nt], Al, Bh[nt]);
                }
            }
            BAR_ARRIVE(4 + buf);             // buffer empty (Y store uses regs only)

            #pragma unroll
            for (int nt = 0; nt < 2; nt++) {
                int n  = wn0 + nt * 8 + 2 * tg;
                int t0 = c * TCH + wm0 + g;
                *reinterpret_cast<float2*>(
                    Y + ((size_t)t0 * NBATCH + b) * NY_ + n) =
                    make_float2(C[nt][0], C[nt][1]);
                *reinterpret_cast<float2*>(
                    Y + ((size_t)(t0 + 8) * NBATCH + b) * NY_ + n) =
                    make_float2(C[nt][2], C[nt][3]);
            }
        }
    }
}

// ---- launch -----------------------------------------------------------------
extern "C" void kernel_launch(void* const* d_in, const int* in_sizes, int n_in,
                              void* d_out, int out_size) {
    const float* y0     = (const float*)d_in[0];
    const float* U      = (const float*)d_in[1];
    const float* lre    = (const float*)d_in[2];
    const float* lim    = (const float*)d_in[3];
    const float* B      = (const float*)d_in[4];
    const float* W_y2x  = (const float*)d_in[5];
    const float* b_y2x  = (const float*)d_in[6];
    const float* W_x2y  = (const float*)d_in[7];
    const float* b_x2y  = (const float*)d_in[8];
    float*       Y      = (float*)d_out;

    cudaFuncSetAttribute(k_fused, cudaFuncAttributeMaxDynamicSharedMemorySize,
                         SMEM_TOTAL);
    k_fused<<<NBATCH, 512, SMEM_TOTAL>>>(y0, U, lre, lim, B, W_y2x, b_y2x,
                                         W_x2y, b_x2y, Y);
}

// round 9
// speedup vs baseline: 1.2634x; 1.2634x over previous
#include <cuda_runtime.h>
#include <cuda_bf16.h>
#include <math.h>
#include <stdint.h>

#define NBATCH  128
#define NH_     256
#define NHC_    128
#define NU_     64
#define NY_     64
#define NCHUNK  32
#define TCH     32

// ---- strides ----------------------------------------------------------------
#define SB_STR  72      // bf16 stride: U/B' planes
#define SW_STR  264     // bf16 stride: W planes
#define SXF     260     // fp32 stride: BuX tile
#define SXP     264     // bf16 stride: X planes

// ---- smem layout (bytes) ----------------------------------------------------
#define OFF_BPHI 0                 // B' hi [256][72] bf16 (rows permuted)
#define OFF_BPLO 36864
#define OFF_WHI  73728             // W hi [64][264] bf16 (k permuted)
#define OFF_WLO  107520
#define OFF_UHI  141312            // U hi [32][72] bf16
#define OFF_ULO  145920
#define OFF_BUX  150528            // BuX fp32 [32][260]
#define OFF_XHI  183808            // X hi plane [32][264] bf16
#define OFF_XLO  200704            // X lo plane
#define OFF_X0   217600            // 256 fp32 (permuted)
#define SMEM_TOTAL 218624

// ---- helpers ----------------------------------------------------------------
__device__ __forceinline__ uint32_t sptr(const void* p) {
    return (uint32_t)__cvta_generic_to_shared(p);
}
__device__ __forceinline__ int permh(int h) {   // hidden-dim re/im interleave
    return (h < NHC_) ? 2 * h : 2 * (h - NHC_) + 1;
}
__device__ __forceinline__ void split2(float a0, float a1, uint32_t& hi, uint32_t& lo) {
    __nv_bfloat16 h0 = __float2bfloat16_rn(a0);
    __nv_bfloat16 h1 = __float2bfloat16_rn(a1);
    __nv_bfloat16 l0 = __float2bfloat16_rn(a0 - __bfloat162float(h0));
    __nv_bfloat16 l1 = __float2bfloat16_rn(a1 - __bfloat162float(h1));
    hi = ((uint32_t)__bfloat16_as_ushort(h1) << 16) | __bfloat16_as_ushort(h0);
    lo = ((uint32_t)__bfloat16_as_ushort(l1) << 16) | __bfloat16_as_ushort(l0);
}
__device__ __forceinline__ void split1(float a, uint16_t& hi, uint16_t& lo) {
    __nv_bfloat16 h = __float2bfloat16_rn(a);
    __nv_bfloat16 l = __float2bfloat16_rn(a - __bfloat162float(h));
    hi = __bfloat16_as_ushort(h);
    lo = __bfloat16_as_ushort(l);
}
__device__ __forceinline__ void mma_bf16(float* c, const uint32_t* a, const uint32_t* b) {
    asm volatile(
        "mma.sync.aligned.m16n8k16.row.col.f32.bf16.bf16.f32 "
        "{%0,%1,%2,%3}, {%4,%5,%6,%7}, {%8,%9}, {%0,%1,%2,%3};"
        : "+f"(c[0]), "+f"(c[1]), "+f"(c[2]), "+f"(c[3])
        : "r"(a[0]), "r"(a[1]), "r"(a[2]), "r"(a[3]), "r"(b[0]), "r"(b[1]));
}
#define LDSM_X4(r0, r1, r2, r3, addr)                                        \
    asm volatile("ldmatrix.sync.aligned.m8n8.x4.shared.b16 {%0,%1,%2,%3}, [%4];" \
                 : "=r"(r0), "=r"(r1), "=r"(r2), "=r"(r3) : "r"(addr))
#define BAR_SYNC(id)   asm volatile("bar.sync %0, 256;"   :: "r"(id) : "memory")
#define BAR_ARRIVE(id) asm volatile("bar.arrive %0, 256;" :: "r"(id) : "memory")
#define BAR_P()        asm volatile("bar.sync 1, 128;" ::: "memory")
// bar 1: producer-internal; bar 2: planes full; bar 3: planes empty

// ---- fused warp-specialized kernel ------------------------------------------
__global__ void __launch_bounds__(256, 1)
k_fused(const float* __restrict__ y0,   const float* __restrict__ U,
        const float* __restrict__ lre,  const float* __restrict__ lim,
        const float* __restrict__ B,    const float* __restrict__ W_y2x,
        const float* __restrict__ b_y2x,const float* __restrict__ W_x2y,
        const float* __restrict__ b_x2y,float* __restrict__ Y) {
    extern __shared__ char sm[];
    int tid  = threadIdx.x;
    int b    = blockIdx.x;
    int lane = tid & 31;
    int g = lane >> 2, tg = lane & 3;
    int j8 = lane >> 3, r8 = lane & 7;

    // ======== init: B' = B*nf, split planes, rows permuted ========
    {
        int h  = tid;
        int n  = permh(h);
        int hc = h & (NHC_ - 1);
        float a  = fabsf(__ldg(lre + hc));
        float nf = sqrtf(1.0f - expf(-2.0f * a));
        const float4* src = reinterpret_cast<const float4*>(B + h * NU_);
        #pragma unroll
        for (int q = 0; q < 16; q++) {
            float4 v = __ldg(src + q);
            v.x *= nf; v.y *= nf; v.z *= nf; v.w *= nf;
            uint32_t h01, l01, h23, l23;
            split2(v.x, v.y, h01, l01);
            split2(v.z, v.w, h23, l23);
            int k = q * 4;
            *(uint32_t*)(sm + OFF_BPHI + (n * SB_STR + k    ) * 2) = h01;
            *(uint32_t*)(sm + OFF_BPHI + (n * SB_STR + k + 2) * 2) = h23;
            *(uint32_t*)(sm + OFF_BPLO + (n * SB_STR + k    ) * 2) = l01;
            *(uint32_t*)(sm + OFF_BPLO + (n * SB_STR + k + 2) * 2) = l23;
        }
    }
    // ======== init: W planes, k permuted ========
    {
        int n    = tid >> 2;
        int part = tid & 3;
        const float4* src = reinterpret_cast<const float4*>(W_x2y + n * NH_ + part * 64);
        #pragma unroll
        for (int q = 0; q < 16; q++) {
            float4 v = __ldg(src + q);
            float vv[4] = {v.x, v.y, v.z, v.w};
            #pragma unroll
            for (int e = 0; e < 4; e++) {
                int newk = permh(part * 64 + q * 4 + e);
                uint16_t hi, lo;
                split1(vv[e], hi, lo);
                *(uint16_t*)(sm + OFF_WHI + (n * SW_STR + newk) * 2) = hi;
                *(uint16_t*)(sm + OFF_WLO + (n * SW_STR + newk) * 2) = lo;
            }
        }
    }
    // ======== init: x0 (permuted store) ========
    {
        float acc = __ldg(b_y2x + tid);
        const float* w = W_y2x + tid * NY_;
        const float* y = y0 + b * NY_;
        #pragma unroll
        for (int k = 0; k < NY_; k++) acc = fmaf(__ldg(y + k), __ldg(w + k), acc);
        ((float*)(sm + OFF_X0))[permh(tid)] = acc;
    }

    // ======== producer U(0) prefetch ========
    int urow = tid >> 2, uq = tid & 3;
    float4 ureg[4];
    if (tid < 128) {
        const float4* src = reinterpret_cast<const float4*>(
            U + ((size_t)urow * NBATCH + b) * NU_);
        #pragma unroll
        for (int j = 0; j < 4; j++) ureg[j] = __ldg(src + uq * 4 + j);
    }
    __syncthreads();

    if (tid < 128) {
        // =================== PRODUCER (warps 0-3) ===================
        float a   = fabsf(__ldg(lre + tid));
        float rr_ = expf(-a);
        float th  = 1.5707963267948966f * __ldg(lim + tid);
        float slr = rr_ * cosf(th);
        float sli = rr_ * sinf(th);
        float2 x0v = ((const float2*)(sm + OFF_X0))[tid];
        float czr = x0v.x, czi = x0v.y;
        int warp = tid >> 5;
        int wn0  = warp * 64;
        int srow = tid >> 2, sq = tid & 3;   // split-pass mapping

        for (int c = 0; c < NCHUNK; c++) {
            // -- STS U(c) planes (prev GEMM reads finished before prev scan) --
            #pragma unroll
            for (int j = 0; j < 4; j++) {
                float4 v = ureg[j];
                uint32_t h01, l01, h23, l23;
                split2(v.x, v.y, h01, l01);
                split2(v.z, v.w, h23, l23);
                int k = uq * 16 + j * 4;
                *(uint32_t*)(sm + OFF_UHI + (urow * SB_STR + k    ) * 2) = h01;
                *(uint32_t*)(sm + OFF_UHI + (urow * SB_STR + k + 2) * 2) = h23;
                *(uint32_t*)(sm + OFF_ULO + (urow * SB_STR + k    ) * 2) = l01;
                *(uint32_t*)(sm + OFF_ULO + (urow * SB_STR + k + 2) * 2) = l23;
            }
            BAR_P();
            if (c < NCHUNK - 1) {
                const float4* src = reinterpret_cast<const float4*>(
                    U + ((size_t)((c + 1) * TCH + urow) * NBATCH + b) * NU_);
                #pragma unroll
                for (int j = 0; j < 4; j++) ureg[j] = __ldg(src + uq * 4 + j);
            }

            // -- Bu GEMM: M=32, warp n-slice 64, K=64 --
            float C[2][8][4];
            #pragma unroll
            for (int mt = 0; mt < 2; mt++)
                #pragma unroll
                for (int nt = 0; nt < 8; nt++)
                    #pragma unroll
                    for (int i = 0; i < 4; i++) C[mt][nt][i] = 0.0f;

            #pragma unroll
            for (int k0 = 0; k0 < 64; k0 += 16) {
                int arow = (j8 & 1) * 8 + r8;
                int acol = k0 + (j8 >> 1) * 8;
                uint32_t Ah[2][4], Al[2][4];
                #pragma unroll
                for (int mt = 0; mt < 2; mt++) {
                    uint32_t ah = sptr(sm + OFF_UHI + ((mt * 16 + arow) * SB_STR + acol) * 2);
                    uint32_t al = sptr(sm + OFF_ULO + ((mt * 16 + arow) * SB_STR + acol) * 2);
                    LDSM_X4(Ah[mt][0], Ah[mt][1], Ah[mt][2], Ah[mt][3], ah);
                    LDSM_X4(Al[mt][0], Al[mt][1], Al[mt][2], Al[mt][3], al);
                }
                uint32_t Bh[8][2], Bl[8][2];
                #pragma unroll
                for (int ntp = 0; ntp < 4; ntp++) {
                    int nrow = wn0 + (ntp * 2 + (j8 >> 1)) * 8 + r8;
                    int bcol = k0 + (j8 & 1) * 8;
                    uint32_t bh = sptr(sm + OFF_BPHI + (nrow * SB_STR + bcol) * 2);
                    uint32_t bl = sptr(sm + OFF_BPLO + (nrow * SB_STR + bcol) * 2);
                    LDSM_X4(Bh[ntp*2][0], Bh[ntp*2][1], Bh[ntp*2+1][0], Bh[ntp*2+1][1], bh);
                    LDSM_X4(Bl[ntp*2][0], Bl[ntp*2][1], Bl[ntp*2+1][0], Bl[ntp*2+1][1], bl);
                }
                #pragma unroll
                for (int mt = 0; mt < 2; mt++)
                    #pragma unroll
                    for (int nt = 0; nt < 8; nt++) {
                        mma_bf16(C[mt][nt], Ah[mt], Bh[nt]);
                        mma_bf16(C[mt][nt], Ah[mt], Bl[nt]);
                        mma_bf16(C[mt][nt], Al[mt], Bh[nt]);
                    }
            }
            // epilogue -> fp32 tile
            float* bx = (float*)(sm + OFF_BUX);
            #pragma unroll
            for (int mt = 0; mt < 2; mt++)
                #pragma unroll
                for (int nt = 0; nt < 8; nt++) {
                    int r = mt * 16 + g;
                    int n = wn0 + nt * 8 + 2 * tg;
                    *(float2*)&bx[r * SXF + n]       = make_float2(C[mt][nt][0], C[mt][nt][1]);
                    *(float2*)&bx[(r + 8) * SXF + n] = make_float2(C[mt][nt][2], C[mt][nt][3]);
                }
            BAR_P();

            // -- scan fp32 in place (re/im adjacent via permutation) --
            {
                float zr = czr, zi = czi;
                #pragma unroll 4
                for (int t = 0; t < TCH; t++) {
                    float2 u = *(const float2*)&bx[t * SXF + 2 * tid];
                    float nr = fmaf(slr, zr, fmaf(-sli, zi, u.x));
                    float ni = fmaf(sli, zr, fmaf( slr, zi, u.y));
                    zr = nr; zi = ni;
                    *(float2*)&bx[t * SXF + 2 * tid] = make_float2(zr, zi);
                }
                czr = zr; czi = zi;
            }
            BAR_SYNC(3);    // wait planes empty (also syncs producer warps post-scan)

            // -- split pass: fp32 tile -> Xhi/Xlo bf16 planes --
            #pragma unroll
            for (int j = 0; j < 16; j++) {
                int col = sq * 64 + j * 4;
                float4 v = *(const float4*)&bx[srow * SXF + col];
                uint32_t h01, l01, h23, l23;
                split2(v.x, v.y, h01, l01);
                split2(v.z, v.w, h23, l23);
                *(uint2*)(sm + OFF_XHI + (srow * SXP + col) * 2) = make_uint2(h01, h23);
                *(uint2*)(sm + OFF_XLO + (srow * SXP + col) * 2) = make_uint2(l01, l23);
            }
            BAR_ARRIVE(2);  // planes full
        }
    } else {
        // =================== CONSUMER (warps 4-7) ===================
        int qw  = (tid >> 5) - 4;
        int wn0 = qw * 16;
        BAR_ARRIVE(3);      // planes initially empty
        float bias0[2], bias1[2];
        #pragma unroll
        for (int nt = 0; nt < 2; nt++) {
            bias0[nt] = __ldg(b_x2y + wn0 + nt * 8 + 2 * tg);
            bias1[nt] = __ldg(b_x2y + wn0 + nt * 8 + 2 * tg + 1);
        }

        for (int c = 0; c < NCHUNK; c++) {
            BAR_SYNC(2);    // wait planes full

            float C[2][2][4];
            #pragma unroll
            for (int mt = 0; mt < 2; mt++)
                #pragma unroll
                for (int nt = 0; nt < 2; nt++) {
                    C[mt][nt][0] = bias0[nt]; C[mt][nt][1] = bias1[nt];
                    C[mt][nt][2] = bias0[nt]; C[mt][nt][3] = bias1[nt];
                }
            #pragma unroll 4
            for (int k0 = 0; k0 < 256; k0 += 16) {
                int arow = (j8 & 1) * 8 + r8;
                int acol = k0 + (j8 >> 1) * 8;
                uint32_t Ah[2][4], Al[2][4];
                #pragma unroll
                for (int mt = 0; mt < 2; mt++) {
                    uint32_t ah = sptr(sm + OFF_XHI + ((mt * 16 + arow) * SXP + acol) * 2);
                    uint32_t al = sptr(sm + OFF_XLO + ((mt * 16 + arow) * SXP + acol) * 2);
                    LDSM_X4(Ah[mt][0], Ah[mt][1], Ah[mt][2], Ah[mt][3], ah);
                    LDSM_X4(Al[mt][0], Al[mt][1], Al[mt][2], Al[mt][3], al);
                }
                uint32_t Bh[2][2], Bl[2][2];
                {
                    int nrow = wn0 + (j8 >> 1) * 8 + r8;
                    int bcol = k0 + (j8 & 1) * 8;
                    uint32_t bh = sptr(sm + OFF_WHI + (nrow * SW_STR + bcol) * 2);
                    uint32_t bl = sptr(sm + OFF_WLO + (nrow * SW_STR + bcol) * 2);
                    LDSM_X4(Bh[0][0], Bh[0][1], Bh[1][0], Bh[1][1], bh);
                    LDSM_X4(Bl[0][0], Bl[0][1], Bl[1][0], Bl[1][1], bl);
                }
                #pragma unroll
                for (int mt = 0; mt < 2; mt++)
                    #pragma unroll
                    for (int nt = 0; nt < 2; nt++) {
                        mma_bf16(C[mt][nt], Ah[mt], Bh[nt]);
                        mma_bf16(C[mt][nt], Ah[mt], Bl[nt]);
                        mma_bf16(C[mt][nt], Al[mt], Bh[nt]);
                    }
            }
            BAR_ARRIVE(3);  // planes empty (Y store uses regs only)

            #pragma unroll
            for (int mt = 0; mt < 2; mt++)
                #pragma unroll
                for (int nt = 0; nt < 2; nt++) {
                    int n  = wn0 + nt * 8 + 2 * tg;
                    int t0 = c * TCH + mt * 16 + g;
                    *reinterpret_cast<float2*>(
                        Y + ((size_t)t0 * NBATCH + b) * NY_ + n) =
                        make_float2(C[mt][nt][0], C[mt][nt][1]);
                    *reinterpret_cast<float2*>(
                        Y + ((size_t)(t0 + 8) * NBATCH + b) * NY_ + n) =
                        make_float2(C[mt][nt][2], C[mt][nt][3]);
                }
        }
    }
}

// ---- launch -----------------------------------------------------------------
extern "C" void kernel_launch(void* const* d_in, const int* in_sizes, int n_in,
                              void* d_out, int out_size) {
    const float* y0     = (const float*)d_in[0];
    const float* U      = (const float*)d_in[1];
    const float* lre    = (const float*)d_in[2];
    const float* lim    = (const float*)d_in[3];
    const float* B      = (const float*)d_in[4];
    const float* W_y2x  = (const float*)d_in[5];
    const float* b_y2x  = (const float*)d_in[6];
    const float* W_x2y  = (const float*)d_in[7];
    const float* b_x2y  = (const float*)d_in[8];
    float*       Y      = (float*)d_out;

    cudaFuncSetAttribute(k_fused, cudaFuncAttributeMaxDynamicSharedMemorySize,
                         SMEM_TOTAL);
    k_fused<<<NBATCH, 256, SMEM_TOTAL>>>(y0, U, lre, lim, B, W_y2x, b_y2x,
                                         W_x2y, b_x2y, Y);
}

// round 10
// speedup vs baseline: 1.8327x; 1.4507x over previous
#include <cuda_runtime.h>
#include <math.h>
#include <stdint.h>

#define NBATCH  128
#define NH_     256
#define NHC_    128
#define NU_     64
#define NY_     64
#define NCHUNK  32
#define TCH     32

// ---- strides (fp32 words) ---------------------------------------------------
#define SBP  68      // B' tile [256][68]
#define SWS  260     // W tile  [64][260]
#define SUS  68      // U tile  [32][68]
#define SXS  260     // BuX     [32][260]

// ---- smem offsets (bytes) ---------------------------------------------------
#define OFF_BP   0                   // 256*68*4 = 69632
#define OFF_W    69632               // 64*260*4 = 66560
#define OFF_U    136192              // 32*68*4  = 8704
#define OFF_BUX0 144896              // 32*260*4 = 33280
#define OFF_BUX1 178176
#define OFF_X0   211456              // 256 fp32
#define SMEM_TOTAL 212480

// ---- helpers ----------------------------------------------------------------
__device__ __forceinline__ int permh(int h) {   // re/im interleave permutation
    return (h < NHC_) ? 2 * h : 2 * (h - NHC_) + 1;
}
__device__ __forceinline__ float tf32r(float a) {
    uint32_t u;
    asm("cvt.rna.tf32.f32 %0, %1;" : "=r"(u) : "f"(a));
    return __uint_as_float(u);
}
__device__ __forceinline__ void mma_tf32(float* c, const float* a, const float* b) {
    asm volatile(
        "mma.sync.aligned.m16n8k8.row.col.f32.tf32.tf32.f32 "
        "{%0,%1,%2,%3}, {%4,%5,%6,%7}, {%8,%9}, {%0,%1,%2,%3};"
        : "+f"(c[0]), "+f"(c[1]), "+f"(c[2]), "+f"(c[3])
        : "r"(__float_as_uint(a[0])), "r"(__float_as_uint(a[1])),
          "r"(__float_as_uint(a[2])), "r"(__float_as_uint(a[3])),
          "r"(__float_as_uint(b[0])), "r"(__float_as_uint(b[1])));
}
#define BAR_SYNC(id)   asm volatile("bar.sync %0, 256;"   :: "r"(id) : "memory")
#define BAR_ARRIVE(id) asm volatile("bar.arrive %0, 256;" :: "r"(id) : "memory")
#define BAR_P()        asm volatile("bar.sync 1, 128;" ::: "memory")
// bar 1: producer internal; 2+buf: buffer full; 4+buf: buffer empty

// ---- fused warp-specialized kernel ------------------------------------------
__global__ void __launch_bounds__(256, 1)
k_fused(const float* __restrict__ y0,   const float* __restrict__ U,
        const float* __restrict__ lre,  const float* __restrict__ lim,
        const float* __restrict__ B,    const float* __restrict__ W_y2x,
        const float* __restrict__ b_y2x,const float* __restrict__ W_x2y,
        const float* __restrict__ b_x2y,float* __restrict__ Y) {
    extern __shared__ char sm[];
    float* sBp = (float*)(sm + OFF_BP);
    float* sW  = (float*)(sm + OFF_W);
    float* sU  = (float*)(sm + OFF_U);
    float* sX0 = (float*)(sm + OFF_X0);

    int tid  = threadIdx.x;
    int b    = blockIdx.x;
    int lane = tid & 31;
    int g = lane >> 2, tg = lane & 3;

    // ======== init: B' = tf32(B*nf), rows permuted ========
    {
        int h  = tid;
        int n  = permh(h);
        int hc = h & (NHC_ - 1);
        float a  = fabsf(__ldg(lre + hc));
        float nf = sqrtf(1.0f - expf(-2.0f * a));
        const float4* src = reinterpret_cast<const float4*>(B + h * NU_);
        #pragma unroll
        for (int q = 0; q < 16; q++) {
            float4 v = __ldg(src + q);
            v.x = tf32r(v.x * nf); v.y = tf32r(v.y * nf);
            v.z = tf32r(v.z * nf); v.w = tf32r(v.w * nf);
            *(float4*)&sBp[n * SBP + q * 4] = v;
        }
    }
    // ======== init: W, k permuted, tf32-rounded ========
    {
        int n    = tid >> 2;
        int part = tid & 3;
        const float4* src = reinterpret_cast<const float4*>(W_x2y + n * NH_ + part * 64);
        #pragma unroll
        for (int q = 0; q < 16; q++) {
            float4 v = __ldg(src + q);
            float vv[4] = {v.x, v.y, v.z, v.w};
            #pragma unroll
            for (int e = 0; e < 4; e++)
                sW[n * SWS + permh(part * 64 + q * 4 + e)] = tf32r(vv[e]);
        }
    }
    // ======== init: x0 (permuted store) ========
    {
        float acc = __ldg(b_y2x + tid);
        const float* w = W_y2x + tid * NY_;
        const float* y = y0 + b * NY_;
        #pragma unroll
        for (int k = 0; k < NY_; k++) acc = fmaf(__ldg(y + k), __ldg(w + k), acc);
        sX0[permh(tid)] = acc;
    }

    // ======== producer U(0) prefetch ========
    int urow = tid >> 2, uq = tid & 3;
    float4 ureg[4];
    if (tid < 128) {
        const float4* src = reinterpret_cast<const float4*>(
            U + ((size_t)urow * NBATCH + b) * NU_);
        #pragma unroll
        for (int j = 0; j < 4; j++) ureg[j] = __ldg(src + uq * 4 + j);
    }
    __syncthreads();

    if (tid < 128) {
        // =================== PRODUCER (warps 0-3) ===================
        float a   = fabsf(__ldg(lre + tid));
        float rr_ = expf(-a);
        float th  = 1.5707963267948966f * __ldg(lim + tid);
        float slr = rr_ * cosf(th);
        float sli = rr_ * sinf(th);
        float czr = sX0[2 * tid], czi = sX0[2 * tid + 1];
        int warp = tid >> 5;
        int wn0  = warp * 64;

        for (int c = 0; c < NCHUNK; c++) {
            int buf = c & 1;
            float* bx = (float*)(sm + (buf ? OFF_BUX1 : OFF_BUX0));
            BAR_SYNC(4 + buf);               // wait buffer empty

            // STS U(c), tf32-rounded
            #pragma unroll
            for (int j = 0; j < 4; j++) {
                float4 v = ureg[j];
                v.x = tf32r(v.x); v.y = tf32r(v.y);
                v.z = tf32r(v.z); v.w = tf32r(v.w);
                *(float4*)&sU[urow * SUS + uq * 16 + j * 4] = v;
            }
            BAR_P();
            if (c < NCHUNK - 1) {
                const float4* src = reinterpret_cast<const float4*>(
                    U + ((size_t)((c + 1) * TCH + urow) * NBATCH + b) * NU_);
                #pragma unroll
                for (int j = 0; j < 4; j++) ureg[j] = __ldg(src + uq * 4 + j);
            }

            // ---- GEMM1: M=32, warp n-slice 64, K=64, single tf32 ----
            float C[2][8][4];
            #pragma unroll
            for (int mt = 0; mt < 2; mt++)
                #pragma unroll
                for (int nt = 0; nt < 8; nt++)
                    #pragma unroll
                    for (int i = 0; i < 4; i++) C[mt][nt][i] = 0.0f;

            #pragma unroll
            for (int k0 = 0; k0 < 64; k0 += 8) {
                float A[2][4];
                #pragma unroll
                for (int mt = 0; mt < 2; mt++) {
                    int r = mt * 16 + g;
                    A[mt][0] = sU[r * SUS + k0 + tg];
                    A[mt][1] = sU[(r + 8) * SUS + k0 + tg];
                    A[mt][2] = sU[r * SUS + k0 + tg + 4];
                    A[mt][3] = sU[(r + 8) * SUS + k0 + tg + 4];
                }
                float Bf[8][2];
                #pragma unroll
                for (int nt = 0; nt < 8; nt++) {
                    int n = wn0 + nt * 8 + g;
                    Bf[nt][0] = sBp[n * SBP + k0 + tg];
                    Bf[nt][1] = sBp[n * SBP + k0 + tg + 4];
                }
                #pragma unroll
                for (int mt = 0; mt < 2; mt++)
                    #pragma unroll
                    for (int nt = 0; nt < 8; nt++)
                        mma_tf32(C[mt][nt], A[mt], Bf[nt]);
            }
            // epilogue -> BuX fp32
            #pragma unroll
            for (int mt = 0; mt < 2; mt++)
                #pragma unroll
                for (int nt = 0; nt < 8; nt++) {
                    int r = mt * 16 + g;
                    int n = wn0 + nt * 8 + 2 * tg;
                    *(float2*)&bx[r * SXS + n]       = make_float2(C[mt][nt][0], C[mt][nt][1]);
                    *(float2*)&bx[(r + 8) * SXS + n] = make_float2(C[mt][nt][2], C[mt][nt][3]);
                }
            BAR_P();

            // ---- scan fp32 (re/im adjacent); store tf32-rounded, carry fp32 --
            {
                float zr = czr, zi = czi;
                #pragma unroll 4
                for (int t = 0; t < TCH; t++) {
                    float2 u = *(const float2*)&bx[t * SXS + 2 * tid];
                    float nr = fmaf(slr, zr, fmaf(-sli, zi, u.x));
                    float ni = fmaf(sli, zr, fmaf( slr, zi, u.y));
                    zr = nr; zi = ni;
                    *(float2*)&bx[t * SXS + 2 * tid] =
                        make_float2(tf32r(zr), tf32r(zi));
                }
                czr = zr; czi = zi;
            }
            BAR_ARRIVE(2 + buf);             // buffer full
        }
    } else {
        // =================== CONSUMER (warps 4-7) ===================
        int qw  = (tid >> 5) - 4;
        int wn0 = qw * 16;
        BAR_ARRIVE(4);
        BAR_ARRIVE(5);
        float bias0[2], bias1[2];
        #pragma unroll
        for (int nt = 0; nt < 2; nt++) {
            bias0[nt] = __ldg(b_x2y + wn0 + nt * 8 + 2 * tg);
            bias1[nt] = __ldg(b_x2y + wn0 + nt * 8 + 2 * tg + 1);
        }

        for (int c = 0; c < NCHUNK; c++) {
            int buf = c & 1;
            const float* bx = (const float*)(sm + (buf ? OFF_BUX1 : OFF_BUX0));
            BAR_SYNC(2 + buf);               // wait full

            float C[2][2][4];
            #pragma unroll
            for (int mt = 0; mt < 2; mt++)
                #pragma unroll
                for (int nt = 0; nt < 2; nt++) {
                    C[mt][nt][0] = bias0[nt]; C[mt][nt][1] = bias1[nt];
                    C[mt][nt][2] = bias0[nt]; C[mt][nt][3] = bias1[nt];
                }
            #pragma unroll 8
            for (int k0 = 0; k0 < 256; k0 += 8) {
                float A[2][4];
                #pragma unroll
                for (int mt = 0; mt < 2; mt++) {
                    int r = mt * 16 + g;
                    A[mt][0] = bx[r * SXS + k0 + tg];
                    A[mt][1] = bx[(r + 8) * SXS + k0 + tg];
                    A[mt][2] = bx[r * SXS + k0 + tg + 4];
                    A[mt][3] = bx[(r + 8) * SXS + k0 + tg + 4];
                }
                float Bf[2][2];
                #pragma unroll
                for (int nt = 0; nt < 2; nt++) {
                    int n = wn0 + nt * 8 + g;
                    Bf[nt][0] = sW[n * SWS + k0 + tg];
                    Bf[nt][1] = sW[n * SWS + k0 + tg + 4];
                }
                #pragma unroll
                for (int mt = 0; mt < 2; mt++)
                    #pragma unroll
                    for (int nt = 0; nt < 2; nt++)
                        mma_tf32(C[mt][nt], A[mt], Bf[nt]);
            }
            BAR_ARRIVE(4 + buf);             // buffer empty (Y store uses regs only)

            #pragma unroll
            for (int mt = 0; mt < 2; mt++)
                #pragma unroll
                for (int nt = 0; nt < 2; nt++) {
                    int n  = wn0 + nt * 8 + 2 * tg;
                    int t0 = c * TCH + mt * 16 + g;
                    *reinterpret_cast<float2*>(
                        Y + ((size_t)t0 * NBATCH + b) * NY_ + n) =
                        make_float2(C[mt][nt][0], C[mt][nt][1]);
                    *reinterpret_cast<float2*>(
                        Y + ((size_t)(t0 + 8) * NBATCH + b) * NY_ + n) =
                        make_float2(C[mt][nt][2], C[mt][nt][3]);
                }
        }
    }
}

// ---- launch -----------------------------------------------------------------
extern "C" void kernel_launch(void* const* d_in, const int* in_sizes, int n_in,
                              void* d_out, int out_size) {
    const float* y0     = (const float*)d_in[0];
    const float* U      = (const float*)d_in[1];
    const float* lre    = (const float*)d_in[2];
    const float* lim    = (const float*)d_in[3];
    const float* B      = (const float*)d_in[4];
    const float* W_y2x  = (const float*)d_in[5];
    const float* b_y2x  = (const float*)d_in[6];
    const float* W_x2y  = (const float*)d_in[7];
    const float* b_x2y  = (const float*)d_in[8];
    float*       Y      = (float*)d_out;

    cudaFuncSetAttribute(k_fused, cudaFuncAttributeMaxDynamicSharedMemorySize,
                         SMEM_TOTAL);
    k_fused<<<NBATCH, 256, SMEM_TOTAL>>>(y0, U, lre, lim, B, W_y2x, b_y2x,
                                         W_x2y, b_x2y, Y);
}

// round 12
// speedup vs baseline: 1.9129x; 1.0437x over previous
#include <cuda_runtime.h>
#include <math.h>
#include <stdint.h>

#define NBATCH  128
#define NH_     256
#define NHC_    128
#define NU_     64
#define NY_     64
#define NCHUNK  32
#define TCH     32

// ---- strides (fp32 words) ---------------------------------------------------
#define SBP  68      // B' tile [256][68]
#define SWS  260     // W tile  [64][260]
#define SUS  68      // U tile  [32][68]
#define SXS  260     // BuX     [32][260]

// ---- smem offsets (bytes) ---------------------------------------------------
#define OFF_BP   0                   // 256*68*4 = 69632
#define OFF_W    69632               // 64*260*4 = 66560
#define OFF_U    136192              // 32*68*4  = 8704
#define OFF_BUX0 144896              // 32*260*4 = 33280
#define OFF_BUX1 178176
#define OFF_X0   211456              // 256 fp32
#define SMEM_TOTAL 212480

// ---- helpers ----------------------------------------------------------------
__device__ __forceinline__ uint32_t sptr(const void* p) {
    return (uint32_t)__cvta_generic_to_shared(p);
}
__device__ __forceinline__ int permh(int h) {   // re/im interleave permutation
    return (h < NHC_) ? 2 * h : 2 * (h - NHC_) + 1;
}
__device__ __forceinline__ float tf32r(float a) {
    uint32_t u;
    asm("cvt.rna.tf32.f32 %0, %1;" : "=r"(u) : "f"(a));
    return __uint_as_float(u);
}
__device__ __forceinline__ void mma_tf32(float* c, const uint32_t* a, const uint32_t* b) {
    asm volatile(
        "mma.sync.aligned.m16n8k8.row.col.f32.tf32.tf32.f32 "
        "{%0,%1,%2,%3}, {%4,%5,%6,%7}, {%8,%9}, {%0,%1,%2,%3};"
        : "+f"(c[0]), "+f"(c[1]), "+f"(c[2]), "+f"(c[3])
        : "r"(a[0]), "r"(a[1]), "r"(a[2]), "r"(a[3]), "r"(b[0]), "r"(b[1]));
}
#define LDSM_X4(r0, r1, r2, r3, addr)                                        \
    asm volatile("ldmatrix.sync.aligned.m8n8.x4.shared.b16 {%0,%1,%2,%3}, [%4];" \
                 : "=r"(r0), "=r"(r1), "=r"(r2), "=r"(r3) : "r"(addr))
#define BAR_SYNC(id)   asm volatile("bar.sync %0, 256;"   :: "r"(id) : "memory")
#define BAR_ARRIVE(id) asm volatile("bar.arrive %0, 256;" :: "r"(id) : "memory")
#define BAR_P()        asm volatile("bar.sync 1, 128;" ::: "memory")
// bar 1: producer internal; 2+buf: buffer full; 4+buf: buffer empty

// ---- fused warp-specialized kernel ------------------------------------------
__global__ void __launch_bounds__(256, 1)
k_fused(const float* __restrict__ y0,   const float* __restrict__ U,
        const float* __restrict__ lre,  const float* __restrict__ lim,
        const float* __restrict__ B,    const float* __restrict__ W_y2x,
        const float* __restrict__ b_y2x,const float* __restrict__ W_x2y,
        const float* __restrict__ b_x2y,float* __restrict__ Y) {
    extern __shared__ char sm[];
    float* sBp = (float*)(sm + OFF_BP);
    float* sW  = (float*)(sm + OFF_W);
    float* sU  = (float*)(sm + OFF_U);
    float* sX0 = (float*)(sm + OFF_X0);

    int tid  = threadIdx.x;
    int b    = blockIdx.x;
    int lane = tid & 31;
    int g = lane >> 2, tg = lane & 3;
    int j8 = lane >> 3, r8 = lane & 7;   // ldmatrix lane mapping

    // ======== init: B' = tf32(B*nf), rows permuted ========
    {
        int h  = tid;
        int n  = permh(h);
        int hc = h & (NHC_ - 1);
        float a  = fabsf(__ldg(lre + hc));
        float nf = sqrtf(1.0f - expf(-2.0f * a));
        const float4* src = reinterpret_cast<const float4*>(B + h * NU_);
        #pragma unroll
        for (int q = 0; q < 16; q++) {
            float4 v = __ldg(src + q);
            v.x = tf32r(v.x * nf); v.y = tf32r(v.y * nf);
            v.z = tf32r(v.z * nf); v.w = tf32r(v.w * nf);
            *(float4*)&sBp[n * SBP + q * 4] = v;
        }
    }
    // ======== init: W, k permuted, tf32-rounded ========
    {
        int n    = tid >> 2;
        int part = tid & 3;
        const float4* src = reinterpret_cast<const float4*>(W_x2y + n * NH_ + part * 64);
        #pragma unroll
        for (int q = 0; q < 16; q++) {
            float4 v = __ldg(src + q);
            float vv[4] = {v.x, v.y, v.z, v.w};
            #pragma unroll
            for (int e = 0; e < 4; e++)
                sW[n * SWS + permh(part * 64 + q * 4 + e)] = tf32r(vv[e]);
        }
    }
    // ======== init: x0 (permuted store) ========
    {
        float acc = __ldg(b_y2x + tid);
        const float* w = W_y2x + tid * NY_;
        const float* y = y0 + b * NY_;
        #pragma unroll
        for (int k = 0; k < NY_; k++) acc = fmaf(__ldg(y + k), __ldg(w + k), acc);
        sX0[permh(tid)] = acc;
    }

    // ======== producer U(0) prefetch ========
    int urow = tid >> 2, uq = tid & 3;
    float4 ureg[4];
    if (tid < 128) {
        const float4* src = reinterpret_cast<const float4*>(
            U + ((size_t)urow * NBATCH + b) * NU_);
        #pragma unroll
        for (int j = 0; j < 4; j++) ureg[j] = __ldg(src + uq * 4 + j);
    }
    __syncthreads();

    if (tid < 128) {
        // =================== PRODUCER (warps 0-3) ===================
        float a   = fabsf(__ldg(lre + tid));
        float rr_ = expf(-a);
        float th  = 1.5707963267948966f * __ldg(lim + tid);
        float slr = rr_ * cosf(th);
        float sli = rr_ * sinf(th);
        float czr = sX0[2 * tid], czi = sX0[2 * tid + 1];
        int warp = tid >> 5;
        int wn0  = warp * 64;

        // LDSM base addresses (per-thread constants)
        uint32_t aU = sptr(sU) + (((j8 & 1) * 8 + r8) * SUS) * 4 + (j8 >> 1) * 16;
        uint32_t aB = sptr(sBp) + ((wn0 + (j8 >> 1) * 8 + r8) * SBP) * 4 + (j8 & 1) * 16;

        for (int c = 0; c < NCHUNK; c++) {
            int buf = c & 1;
            float* bx = (float*)(sm + (buf ? OFF_BUX1 : OFF_BUX0));
            BAR_SYNC(4 + buf);               // wait buffer empty

            // STS U(c), tf32-rounded
            #pragma unroll
            for (int j = 0; j < 4; j++) {
                float4 v = ureg[j];
                v.x = tf32r(v.x); v.y = tf32r(v.y);
                v.z = tf32r(v.z); v.w = tf32r(v.w);
                *(float4*)&sU[urow * SUS + uq * 16 + j * 4] = v;
            }
            BAR_P();
            if (c < NCHUNK - 1) {
                const float4* src = reinterpret_cast<const float4*>(
                    U + ((size_t)((c + 1) * TCH + urow) * NBATCH + b) * NU_);
                #pragma unroll
                for (int j = 0; j < 4; j++) ureg[j] = __ldg(src + uq * 4 + j);
            }

            // ---- GEMM1: M=32, warp n-slice 64, K=64, single tf32 ----
            float C[2][8][4];
            #pragma unroll
            for (int mt = 0; mt < 2; mt++)
                #pragma unroll
                for (int nt = 0; nt < 8; nt++)
                    #pragma unroll
                    for (int i = 0; i < 4; i++) C[mt][nt][i] = 0.0f;

            #pragma unroll
            for (int k0 = 0; k0 < 64; k0 += 8) {
                uint32_t A[2][4];
                #pragma unroll
                for (int mt = 0; mt < 2; mt++)
                    LDSM_X4(A[mt][0], A[mt][1], A[mt][2], A[mt][3],
                            aU + (mt * 16 * SUS + k0) * 4);
                uint32_t Bf[8][2];
                #pragma unroll
                for (int ntp = 0; ntp < 4; ntp++)
                    LDSM_X4(Bf[ntp*2][0], Bf[ntp*2][1], Bf[ntp*2+1][0], Bf[ntp*2+1][1],
                            aB + (ntp * 16 * SBP + k0) * 4);
                #pragma unroll
                for (int mt = 0; mt < 2; mt++)
                    #pragma unroll
                    for (int nt = 0; nt < 8; nt++)
                        mma_tf32(C[mt][nt], A[mt], Bf[nt]);
            }
            // epilogue -> BuX fp32
            #pragma unroll
            for (int mt = 0; mt < 2; mt++)
                #pragma unroll
                for (int nt = 0; nt < 8; nt++) {
                    int r = mt * 16 + g;
                    int n = wn0 + nt * 8 + 2 * tg;
                    *(float2*)&bx[r * SXS + n]       = make_float2(C[mt][nt][0], C[mt][nt][1]);
                    *(float2*)&bx[(r + 8) * SXS + n] = make_float2(C[mt][nt][2], C[mt][nt][3]);
                }
            BAR_P();

            // ---- scan fp32 (re/im adjacent); store tf32-rounded, carry fp32 --
            {
                float zr = czr, zi = czi;
                #pragma unroll 4
                for (int t = 0; t < TCH; t++) {
                    float2 u = *(const float2*)&bx[t * SXS + 2 * tid];
                    float nr = fmaf(slr, zr, fmaf(-sli, zi, u.x));
                    float ni = fmaf(sli, zr, fmaf( slr, zi, u.y));
                    zr = nr; zi = ni;
                    *(float2*)&bx[t * SXS + 2 * tid] =
                        make_float2(tf32r(zr), tf32r(zi));
                }
                czr = zr; czi = zi;
            }
            BAR_ARRIVE(2 + buf);             // buffer full
        }
    } else {
        // =================== CONSUMER (warps 4-7) ===================
        int qw  = (tid >> 5) - 4;
        int wn0 = qw * 16;
        BAR_ARRIVE(4);
        BAR_ARRIVE(5);
        float bias0[2], bias1[2];
        #pragma unroll
        for (int nt = 0; nt < 2; nt++) {
            bias0[nt] = __ldg(b_x2y + wn0 + nt * 8 + 2 * tg);
            bias1[nt] = __ldg(b_x2y + wn0 + nt * 8 + 2 * tg + 1);
        }
        // LDSM base addresses
        uint32_t aW = sptr(sW) + ((wn0 + (j8 >> 1) * 8 + r8) * SWS) * 4 + (j8 & 1) * 16;
        uint32_t aX0b = (((j8 & 1) * 8 + r8) * SXS) * 4 + (j8 >> 1) * 16;

        for (int c = 0; c < NCHUNK; c++) {
            int buf = c & 1;
            const float* bx = (const float*)(sm + (buf ? OFF_BUX1 : OFF_BUX0));
            uint32_t aX = sptr(bx) + aX0b;
            BAR_SYNC(2 + buf);               // wait full

            float C[2][2][4];
            #pragma unroll
            for (int mt = 0; mt < 2; mt++)
                #pragma unroll
                for (int nt = 0; nt < 2; nt++) {
                    C[mt][nt][0] = bias0[nt]; C[mt][nt][1] = bias1[nt];
                    C[mt][nt][2] = bias0[nt]; C[mt][nt][3] = bias1[nt];
                }
            #pragma unroll 8
            for (int k0 = 0; k0 < 256; k0 += 8) {
                uint32_t A[2][4];
                #pragma unroll
                for (int mt = 0; mt < 2; mt++)
                    LDSM_X4(A[mt][0], A[mt][1], A[mt][2], A[mt][3],
                            aX + (mt * 16 * SXS + k0) * 4);
                uint32_t Bf[2][2];
                LDSM_X4(Bf[0][0], Bf[0][1], Bf[1][0], Bf[1][1], aW + k0 * 4);
                #pragma unroll
                for (int mt = 0; mt < 2; mt++)
                    #pragma unroll
                    for (int nt = 0; nt < 2; nt++)
                        mma_tf32(C[mt][nt], A[mt], Bf[nt]);
            }
            BAR_ARRIVE(4 + buf);             // buffer empty (Y store uses regs only)

            #pragma unroll
            for (int mt = 0; mt < 2; mt++)
                #pragma unroll
                for (int nt = 0; nt < 2; nt++) {
                    int n  = wn0 + nt * 8 + 2 * tg;
                    int t0 = c * TCH + mt * 16 + g;
                    *reinterpret_cast<float2*>(
                        Y + ((size_t)t0 * NBATCH + b) * NY_ + n) =
                        make_float2(C[mt][nt][0], C[mt][nt][1]);
                    *reinterpret_cast<float2*>(
                        Y + ((size_t)(t0 + 8) * NBATCH + b) * NY_ + n) =
                        make_float2(C[mt][nt][2], C[mt][nt][3]);
                }
        }
    }
}

// ---- launch -----------------------------------------------------------------
extern "C" void kernel_launch(void* const* d_in, const int* in_sizes, int n_in,
                              void* d_out, int out_size) {
    const float* y0     = (const float*)d_in[0];
    const float* U      = (const float*)d_in[1];
    const float* lre    = (const float*)d_in[2];
    const float* lim    = (const float*)d_in[3];
    const float* B      = (const float*)d_in[4];
    const float* W_y2x  = (const float*)d_in[5];
    const float* b_y2x  = (const float*)d_in[6];
    const float* W_x2y  = (const float*)d_in[7];
    const float* b_x2y  = (const float*)d_in[8];
    float*       Y      = (float*)d_out;

    cudaFuncSetAttribute(k_fused, cudaFuncAttributeMaxDynamicSharedMemorySize,
                         SMEM_TOTAL);
    k_fused<<<NBATCH, 256, SMEM_TOTAL>>>(y0, U, lre, lim, B, W_y2x, b_y2x,
                                         W_x2y, b_x2y, Y);
}

// round 14
// speedup vs baseline: 2.0044x; 1.0479x over previous
#include <cuda_runtime.h>
#include <math.h>
#include <stdint.h>

#define NBATCH  128
#define NH_     256
#define NHC_    128
#define NU_     64
#define NY_     64
#define NCHUNK  32
#define TCH     32

// ---- strides (fp32 words) ---------------------------------------------------
#define SBP  68      // B' tile [256][68]
#define SWS  260     // W tile  [64][260]
#define SUS  68      // U tile  [32][68]
#define SXS  260     // BuX     [32][260]

// ---- smem offsets (bytes) ---------------------------------------------------
#define OFF_BP   0                   // 256*68*4 = 69632
#define OFF_W    69632               // 64*260*4 = 66560
#define OFF_U    136192              // 32*68*4  = 8704
#define OFF_BUX0 144896              // 32*260*4 = 33280
#define OFF_BUX1 178176
#define OFF_X0   211456              // 256 fp32
#define SMEM_TOTAL 212480

// ---- helpers ----------------------------------------------------------------
__device__ __forceinline__ uint32_t sptr(const void* p) {
    return (uint32_t)__cvta_generic_to_shared(p);
}
__device__ __forceinline__ int permh(int h) {   // re/im interleave permutation
    return (h < NHC_) ? 2 * h : 2 * (h - NHC_) + 1;
}
__device__ __forceinline__ float tf32r(float a) {
    uint32_t u;
    asm("cvt.rna.tf32.f32 %0, %1;" : "=r"(u) : "f"(a));
    return __uint_as_float(u);
}
__device__ __forceinline__ void mma_tf32(float* c, const uint32_t* a, const uint32_t* b) {
    asm volatile(
        "mma.sync.aligned.m16n8k8.row.col.f32.tf32.tf32.f32 "
        "{%0,%1,%2,%3}, {%4,%5,%6,%7}, {%8,%9}, {%0,%1,%2,%3};"
        : "+f"(c[0]), "+f"(c[1]), "+f"(c[2]), "+f"(c[3])
        : "r"(a[0]), "r"(a[1]), "r"(a[2]), "r"(a[3]), "r"(b[0]), "r"(b[1]));
}
#define LDSM_X4(r0, r1, r2, r3, addr)                                        \
    asm volatile("ldmatrix.sync.aligned.m8n8.x4.shared.b16 {%0,%1,%2,%3}, [%4];" \
                 : "=r"(r0), "=r"(r1), "=r"(r2), "=r"(r3) : "r"(addr))
#define BAR_SYNC(id)   asm volatile("bar.sync %0, 256;"   :: "r"(id) : "memory")
#define BAR_ARRIVE(id) asm volatile("bar.arrive %0, 256;" :: "r"(id) : "memory")
#define BAR_P()        asm volatile("bar.sync 1, 128;" ::: "memory")
// bar 1: producer internal; 2+buf: buffer full; 4+buf: buffer empty

// ---- fused warp-specialized kernel ------------------------------------------
__global__ void __launch_bounds__(256, 1)
k_fused(const float* __restrict__ y0,   const float* __restrict__ U,
        const float* __restrict__ lre,  const float* __restrict__ lim,
        const float* __restrict__ B,    const float* __restrict__ W_y2x,
        const float* __restrict__ b_y2x,const float* __restrict__ W_x2y,
        const float* __restrict__ b_x2y,float* __restrict__ Y) {
    extern __shared__ char sm[];
    float* sBp = (float*)(sm + OFF_BP);
    float* sW  = (float*)(sm + OFF_W);
    float* sU  = (float*)(sm + OFF_U);
    float* sX0 = (float*)(sm + OFF_X0);

    int tid  = threadIdx.x;
    int b    = blockIdx.x;
    int lane = tid & 31;
    int g = lane >> 2, tg = lane & 3;
    int j8 = lane >> 3, r8 = lane & 7;   // ldmatrix lane mapping

    // ======== init: B' = tf32(B*nf), rows permuted ========
    {
        int h  = tid;
        int n  = permh(h);
        int hc = h & (NHC_ - 1);
        float a  = fabsf(__ldg(lre + hc));
        float nf = sqrtf(1.0f - expf(-2.0f * a));
        const float4* src = reinterpret_cast<const float4*>(B + h * NU_);
        #pragma unroll
        for (int q = 0; q < 16; q++) {
            float4 v = __ldg(src + q);
            v.x = tf32r(v.x * nf); v.y = tf32r(v.y * nf);
            v.z = tf32r(v.z * nf); v.w = tf32r(v.w * nf);
            *(float4*)&sBp[n * SBP + q * 4] = v;
        }
    }
    // ======== init: W, k permuted, tf32-rounded ========
    {
        int n    = tid >> 2;
        int part = tid & 3;
        const float4* src = reinterpret_cast<const float4*>(W_x2y + n * NH_ + part * 64);
        #pragma unroll
        for (int q = 0; q < 16; q++) {
            float4 v = __ldg(src + q);
            float vv[4] = {v.x, v.y, v.z, v.w};
            #pragma unroll
            for (int e = 0; e < 4; e++)
                sW[n * SWS + permh(part * 64 + q * 4 + e)] = tf32r(vv[e]);
        }
    }
    // ======== init: x0 (permuted store) ========
    {
        float acc = __ldg(b_y2x + tid);
        const float* w = W_y2x + tid * NY_;
        const float* y = y0 + b * NY_;
        #pragma unroll
        for (int k = 0; k < NY_; k++) acc = fmaf(__ldg(y + k), __ldg(w + k), acc);
        sX0[permh(tid)] = acc;
    }

    // ======== producer U(0) prefetch ========
    int urow = tid >> 2, uq = tid & 3;
    float4 ureg[4];
    if (tid < 128) {
        const float4* src = reinterpret_cast<const float4*>(
            U + ((size_t)urow * NBATCH + b) * NU_);
        #pragma unroll
        for (int j = 0; j < 4; j++) ureg[j] = __ldg(src + uq * 4 + j);
    }
    __syncthreads();

    if (tid < 128) {
        // =================== PRODUCER (warps 0-3) ===================
        float a   = fabsf(__ldg(lre + tid));
        float rr_ = expf(-a);
        float th  = 1.5707963267948966f * __ldg(lim + tid);
        float slr = rr_ * cosf(th);
        float sli = rr_ * sinf(th);
        float czr = sX0[2 * tid], czi = sX0[2 * tid + 1];
        int warp = tid >> 5;
        int wn0  = warp * 64;

        // LDSM base addresses (per-thread constants)
        uint32_t aU = sptr(sU) + (((j8 & 1) * 8 + r8) * SUS) * 4 + (j8 >> 1) * 16;
        uint32_t aB = sptr(sBp) + ((wn0 + (j8 >> 1) * 8 + r8) * SBP) * 4 + (j8 & 1) * 16;

        // ---- hoist B' fragments for K in [0,32): 4 ksteps x 8 n8 x 2 regs ----
        uint32_t Bfr[4][8][2];
        #pragma unroll
        for (int ks = 0; ks < 4; ks++)
            #pragma unroll
            for (int ntp = 0; ntp < 4; ntp++)
                LDSM_X4(Bfr[ks][ntp*2][0], Bfr[ks][ntp*2][1],
                        Bfr[ks][ntp*2+1][0], Bfr[ks][ntp*2+1][1],
                        aB + (ntp * 16 * SBP + ks * 8) * 4);

        for (int c = 0; c < NCHUNK; c++) {
            int buf = c & 1;
            float* bx = (float*)(sm + (buf ? OFF_BUX1 : OFF_BUX0));
            BAR_SYNC(4 + buf);               // wait buffer empty

            // STS U(c), tf32-rounded
            #pragma unroll
            for (int j = 0; j < 4; j++) {
                float4 v = ureg[j];
                v.x = tf32r(v.x); v.y = tf32r(v.y);
                v.z = tf32r(v.z); v.w = tf32r(v.w);
                *(float4*)&sU[urow * SUS + uq * 16 + j * 4] = v;
            }
            BAR_P();
            if (c < NCHUNK - 1) {
                const float4* src = reinterpret_cast<const float4*>(
                    U + ((size_t)((c + 1) * TCH + urow) * NBATCH + b) * NU_);
                #pragma unroll
                for (int j = 0; j < 4; j++) ureg[j] = __ldg(src + uq * 4 + j);
            }

            // ---- GEMM1: M=32, warp n-slice 64, K=64, single tf32 ----
            float C[2][8][4];
            #pragma unroll
            for (int mt = 0; mt < 2; mt++)
                #pragma unroll
                for (int nt = 0; nt < 8; nt++)
                    #pragma unroll
                    for (int i = 0; i < 4; i++) C[mt][nt][i] = 0.0f;

            // K in [0,32): B' from hoisted registers
            #pragma unroll
            for (int ks = 0; ks < 4; ks++) {
                int k0 = ks * 8;
                uint32_t A[2][4];
                #pragma unroll
                for (int mt = 0; mt < 2; mt++)
                    LDSM_X4(A[mt][0], A[mt][1], A[mt][2], A[mt][3],
                            aU + (mt * 16 * SUS + k0) * 4);
                #pragma unroll
                for (int mt = 0; mt < 2; mt++)
                    #pragma unroll
                    for (int nt = 0; nt < 8; nt++)
                        mma_tf32(C[mt][nt], A[mt], Bfr[ks][nt]);
            }
            // K in [32,64): B' streamed from smem
            #pragma unroll
            for (int ks = 4; ks < 8; ks++) {
                int k0 = ks * 8;
                uint32_t A[2][4];
                #pragma unroll
                for (int mt = 0; mt < 2; mt++)
                    LDSM_X4(A[mt][0], A[mt][1], A[mt][2], A[mt][3],
                            aU + (mt * 16 * SUS + k0) * 4);
                uint32_t Bf[8][2];
                #pragma unroll
                for (int ntp = 0; ntp < 4; ntp++)
                    LDSM_X4(Bf[ntp*2][0], Bf[ntp*2][1], Bf[ntp*2+1][0], Bf[ntp*2+1][1],
                            aB + (ntp * 16 * SBP + k0) * 4);
                #pragma unroll
                for (int mt = 0; mt < 2; mt++)
                    #pragma unroll
                    for (int nt = 0; nt < 8; nt++)
                        mma_tf32(C[mt][nt], A[mt], Bf[nt]);
            }
            // epilogue -> BuX fp32
            #pragma unroll
            for (int mt = 0; mt < 2; mt++)
                #pragma unroll
                for (int nt = 0; nt < 8; nt++) {
                    int r = mt * 16 + g;
                    int n = wn0 + nt * 8 + 2 * tg;
                    *(float2*)&bx[r * SXS + n]       = make_float2(C[mt][nt][0], C[mt][nt][1]);
                    *(float2*)&bx[(r + 8) * SXS + n] = make_float2(C[mt][nt][2], C[mt][nt][3]);
                }
            BAR_P();

            // ---- scan fp32 (re/im adjacent); store tf32-rounded, carry fp32 --
            {
                float zr = czr, zi = czi;
                #pragma unroll 4
                for (int t = 0; t < TCH; t++) {
                    float2 u = *(const float2*)&bx[t * SXS + 2 * tid];
                    float nr = fmaf(slr, zr, fmaf(-sli, zi, u.x));
                    float ni = fmaf(sli, zr, fmaf( slr, zi, u.y));
                    zr = nr; zi = ni;
                    *(float2*)&bx[t * SXS + 2 * tid] =
                        make_float2(tf32r(zr), tf32r(zi));
                }
                czr = zr; czi = zi;
            }
            BAR_ARRIVE(2 + buf);             // buffer full
        }
    } else {
        // =================== CONSUMER (warps 4-7) ===================
        int qw  = (tid >> 5) - 4;
        int wn0 = qw * 16;
        BAR_ARRIVE(4);
        BAR_ARRIVE(5);
        float bias0[2], bias1[2];
        #pragma unroll
        for (int nt = 0; nt < 2; nt++) {
            bias0[nt] = __ldg(b_x2y + wn0 + nt * 8 + 2 * tg);
            bias1[nt] = __ldg(b_x2y + wn0 + nt * 8 + 2 * tg + 1);
        }
        // LDSM base addresses
        uint32_t aW = sptr(sW) + ((wn0 + (j8 >> 1) * 8 + r8) * SWS) * 4 + (j8 & 1) * 16;
        uint32_t aX0b = (((j8 & 1) * 8 + r8) * SXS) * 4 + (j8 >> 1) * 16;

        // ---- hoist the ENTIRE W fragment set: 32 ksteps x 2 n8 x 2 regs ----
        uint32_t Wfr[32][2][2];
        #pragma unroll
        for (int ks = 0; ks < 32; ks++)
            LDSM_X4(Wfr[ks][0][0], Wfr[ks][0][1], Wfr[ks][1][0], Wfr[ks][1][1],
                    aW + ks * 32);

        for (int c = 0; c < NCHUNK; c++) {
            int buf = c & 1;
            const float* bx = (const float*)(sm + (buf ? OFF_BUX1 : OFF_BUX0));
            uint32_t aX = sptr(bx) + aX0b;
            BAR_SYNC(2 + buf);               // wait full

            float C[2][2][4];
            #pragma unroll
            for (int mt = 0; mt < 2; mt++)
                #pragma unroll
                for (int nt = 0; nt < 2; nt++) {
                    C[mt][nt][0] = bias0[nt]; C[mt][nt][1] = bias1[nt];
                    C[mt][nt][2] = bias0[nt]; C[mt][nt][3] = bias1[nt];
                }
            #pragma unroll
            for (int ks = 0; ks < 32; ks++) {
                int k0 = ks * 8;
                uint32_t A[2][4];
                #pragma unroll
                for (int mt = 0; mt < 2; mt++)
                    LDSM_X4(A[mt][0], A[mt][1], A[mt][2], A[mt][3],
                            aX + (mt * 16 * SXS + k0) * 4);
                #pragma unroll
                for (int mt = 0; mt < 2; mt++)
                    #pragma unroll
                    for (int nt = 0; nt < 2; nt++)
                        mma_tf32(C[mt][nt], A[mt], Wfr[ks][nt]);
            }
            BAR_ARRIVE(4 + buf);             // buffer empty (Y store uses regs only)

            #pragma unroll
            for (int mt = 0; mt < 2; mt++)
                #pragma unroll
                for (int nt = 0; nt < 2; nt++) {
                    int n  = wn0 + nt * 8 + 2 * tg;
                    int t0 = c * TCH + mt * 16 + g;
                    *reinterpret_cast<float2*>(
                        Y + ((size_t)t0 * NBATCH + b) * NY_ + n) =
                        make_float2(C[mt][nt][0], C[mt][nt][1]);
                    *reinterpret_cast<float2*>(
                        Y + ((size_t)(t0 + 8) * NBATCH + b) * NY_ + n) =
                        make_float2(C[mt][nt][2], C[mt][nt][3]);
                }
        }
    }
}

// ---- launch -----------------------------------------------------------------
extern "C" void kernel_launch(void* const* d_in, const int* in_sizes, int n_in,
                              void* d_out, int out_size) {
    const float* y0     = (const float*)d_in[0];
    const float* U      = (const float*)d_in[1];
    const float* lre    = (const float*)d_in[2];
    const float* lim    = (const float*)d_in[3];
    const float* B      = (const float*)d_in[4];
    const float* W_y2x  = (const float*)d_in[5];
    const float* b_y2x  = (const float*)d_in[6];
    const float* W_x2y  = (const float*)d_in[7];
    const float* b_x2y  = (const float*)d_in[8];
    float*       Y      = (float*)d_out;

    cudaFuncSetAttribute(k_fused, cudaFuncAttributeMaxDynamicSharedMemorySize,
                         SMEM_TOTAL);
    k_fused<<<NBATCH, 256, SMEM_TOTAL>>>(y0, U, lre, lim, B, W_y2x, b_y2x,
                                         W_x2y, b_x2y, Y);
}